// round 15
// baseline (speedup 1.0000x reference)
#include <cuda_runtime.h>
#include <math.h>
#include <stdint.h>

#define FULL 0xffffffffu
typedef unsigned long long u64;
typedef unsigned int u32;

static constexpr int P    = 16;
static constexpr int NBLK = 296;

// ---------------- scratch (__device__ globals; no allocations) ----------------
__device__ float4 g_Rtab0[32 * 32];     // rel @ W_ih[:, :32]^T           (no bias)
__device__ float4 g_Etab0[32 * 32];     // bias + ent @ W_ih[:, 32:]^T    (bias folded)
__device__ float4 g_Rtab1[32 * 32];
__device__ float4 g_Etab1[32 * 32];
__device__ float4 g_RT0[1024 * 32];     // RT[ti*32+ri] = Rtab[ri] + Etab'[ti]
__device__ float4 g_RT1[1024 * 32];
__device__ float  g_lossblk[NBLK];
__device__ int    g_donecnt;

// ---------------- math helpers ----------------
__device__ __forceinline__ float tanha(float x) {
    float y; asm("tanh.approx.f32 %0,%1;" : "=f"(y) : "f"(x)); return y;
}
__device__ __forceinline__ float sigf(float x) {
    return fmaf(tanha(0.5f * x), 0.5f, 0.5f);
}
// pack {lo, hi} into bf16x2 (PTX: first source -> high half)
__device__ __forceinline__ u32 bfpack(float lo, float hi) {
    u32 d; asm("cvt.rn.bf16x2.f32 %0,%1,%2;" : "=r"(d) : "f"(hi), "f"(lo)); return d;
}
// D(16x8 f32) += A(16x16 bf16,row) @ B(16x8 bf16,col)
__device__ __forceinline__ void mma_bf16(float& d0, float& d1, float& d2, float& d3,
                                         u32 a0, u32 a1, u32 a2, u32 a3,
                                         u32 b0, u32 b1) {
    asm("mma.sync.aligned.m16n8k16.row.col.f32.bf16.bf16.f32 "
        "{%0,%1,%2,%3},{%4,%5,%6,%7},{%8,%9},{%0,%1,%2,%3};"
        : "+f"(d0), "+f"(d1), "+f"(d2), "+f"(d3)
        : "r"(a0), "r"(a1), "r"(a2), "r"(a3), "r"(b0), "r"(b1));
}

// ---------------- precompute E/R contribution tables (tiny) ----------------
__global__ void precompute_tables_kernel(const float* __restrict__ rel_table,
                                         const float* __restrict__ ent_table,
                                         const float* __restrict__ wih0,
                                         const float* __restrict__ wih1,
                                         const float* __restrict__ bih0,
                                         const float* __restrict__ bhh0,
                                         const float* __restrict__ bih1,
                                         const float* __restrict__ bhh1) {
    int tid   = threadIdx.x;          // 1024
    int which = blockIdx.x;           // 0:Rtab0 1:Etab0 2:Rtab1 3:Etab1
    int r     = tid >> 5;
    int lane  = tid & 31;
    const float* w   = (which < 2) ? wih0 : wih1;
    const float* src = (which & 1) ? ent_table : rel_table;
    int colofs       = (which & 1) ? 32 : 0;

    float4 acc = make_float4(0.f, 0.f, 0.f, 0.f);
    if (which & 1) {  // Etab: fold bias in
        const float* bi = (which < 2) ? bih0 : bih1;
        const float* bh = (which < 2) ? bhh0 : bhh1;
        acc.x = bi[lane]      + bh[lane];
        acc.y = bi[32 + lane] + bh[32 + lane];
        acc.z = bi[64 + lane] + bh[64 + lane];
        acc.w = bi[96 + lane] + bh[96 + lane];
    }
    #pragma unroll
    for (int k = 0; k < 32; k++) {
        float x = src[r * 32 + k];
        acc.x += x * w[(0 * 32 + lane) * 64 + colofs + k];
        acc.y += x * w[(1 * 32 + lane) * 64 + colofs + k];
        acc.z += x * w[(2 * 32 + lane) * 64 + colofs + k];
        acc.w += x * w[(3 * 32 + lane) * 64 + colofs + k];
    }
    float4* dst = (which == 0) ? g_Rtab0 : (which == 1) ? g_Etab0
                : (which == 2) ? g_Rtab1 : g_Etab1;
    dst[tid] = acc;
}

// ---------------- precompute fused RT tables: RT[ti*32+ri] = Rtab[ri] + Etab'[ti] ----------------
__global__ void precompute_rt_kernel() {
    if (blockIdx.x == 0 && blockIdx.y == 0 && threadIdx.x == 0)
        g_donecnt = 0;   // reset last-block counter for this launch's fused kernel
    int hop = blockIdx.y;
    int i = blockIdx.x * 256 + threadIdx.x;   // [0, 32768)
    int comb = i >> 5, j = i & 31;
    int ti = comb >> 5, r = comb & 31;
    const float4* Rt = hop ? g_Rtab1 : g_Rtab0;
    const float4* Et = hop ? g_Etab1 : g_Etab0;
    float4 a = Rt[r * 32 + j], b = Et[ti * 32 + j];
    (hop ? g_RT1 : g_RT0)[comb * 32 + j] =
        make_float4(a.x + b.x, a.y + b.y, a.z + b.z, a.w + b.w);
}

// ---------------- 16-path LSTM body (bf16 MMA, f32 tables) ----------------
// h_d out in D-fragment layout: flat = jt*4 + (pathB?2:0) + cc
template <int NSTEP>
__device__ __forceinline__ void lstm16(
        const uint4* __restrict__ Bs2, const uint4* __restrict__ BsU,
        const float4* __restrict__ Etab4, const float4* __restrict__ RTtab,
        u32 au0, u32 au1, u32 au2, u32 au3,
        u32 idxA, u32 idxB, int t, int lane, float h_d[16]) {
    float c_st[16];
    // ---- step 0: D init = Etab'[seed] (bias folded), U-term via broadcast MMA ----
    {
        const float4* EA = Etab4 + (idxA & 31) * 32;
        const float4* EB = Etab4 + (idxB & 31) * 32;
        #pragma unroll
        for (int jt = 0; jt < 4; jt++) {
            float G[4][4];
            #pragma unroll
            for (int cc = 0; cc < 2; cc++) {
                int j = 8 * jt + 2 * t + cc;
                float4 ea = EA[j];
                G[0][cc] = ea.x; G[1][cc] = ea.y; G[2][cc] = ea.z; G[3][cc] = ea.w;
                float4 eb = EB[j];
                G[0][2 + cc] = eb.x; G[1][2 + cc] = eb.y;
                G[2][2 + cc] = eb.z; G[3][2 + cc] = eb.w;
            }
            #pragma unroll
            for (int gt = 0; gt < 4; gt++) {
                int nt = jt + 4 * gt;
                uint4 bu = BsU[nt * 32 + lane];
                mma_bf16(G[gt][0], G[gt][1], G[gt][2], G[gt][3],
                         au0, au0, au1, au1, bu.x, bu.y);
                mma_bf16(G[gt][0], G[gt][1], G[gt][2], G[gt][3],
                         au2, au2, au3, au3, bu.z, bu.w);
            }
            #pragma unroll
            for (int dq = 0; dq < 4; dq++) {
                int ci = jt * 4 + dq;
                float c = sigf(G[0][dq]) * tanha(G[2][dq]);   // c_prev = 0
                c_st[ci] = c;
                h_d[ci] = sigf(G[3][dq]) * tanha(c);
            }
        }
    }
    // ---- recurrent steps ----
    #pragma unroll
    for (int s = 1; s < NSTEP; s++) {
        u32 ah[8];   // D-frag == A-frag for bf16 k16: same-lane packs only
        #pragma unroll
        for (int q = 0; q < 8; q++)
            ah[q] = bfpack(h_d[q * 2], h_d[q * 2 + 1]);

        u32 cA = (idxA >> (5 * (2 * s - 1))) & 1023;   // combined ti*32+ri
        u32 cB = (idxB >> (5 * (2 * s - 1))) & 1023;
        const float4* RTA = RTtab + cA * 32;
        const float4* RTB = RTtab + cB * 32;

        #pragma unroll
        for (int jt = 0; jt < 4; jt++) {
            float G[4][4];
            #pragma unroll
            for (int cc = 0; cc < 2; cc++) {
                int j = 8 * jt + 2 * t + cc;
                float4 ra = RTA[j];
                G[0][cc] = ra.x; G[1][cc] = ra.y; G[2][cc] = ra.z; G[3][cc] = ra.w;
                float4 rb = RTB[j];
                G[0][2 + cc] = rb.x; G[1][2 + cc] = rb.y;
                G[2][2 + cc] = rb.z; G[3][2 + cc] = rb.w;
            }
            #pragma unroll
            for (int gt = 0; gt < 4; gt++) {
                int nt = jt + 4 * gt;
                uint4 bb = Bs2[nt * 32 + lane];
                mma_bf16(G[gt][0], G[gt][1], G[gt][2], G[gt][3],
                         ah[0], ah[1], ah[2], ah[3], bb.x, bb.y);
                mma_bf16(G[gt][0], G[gt][1], G[gt][2], G[gt][3],
                         ah[4], ah[5], ah[6], ah[7], bb.z, bb.w);
            }
            #pragma unroll
            for (int dq = 0; dq < 4; dq++) {
                int ci = jt * 4 + dq;
                float c = sigf(G[1][dq]) * c_st[ci] + sigf(G[0][dq]) * tanha(G[2][dq]);
                c_st[ci] = c;
                h_d[ci] = sigf(G[3][dq]) * tanha(c);
            }
        }
    }
}

// reduce 16 paths -> per-b sum, stage to lane=j layout via smem, return f[lane]
__device__ __forceinline__ float reduce_stage(float h_d[16], float* sfw, int lane) {
    #pragma unroll
    for (int jt = 0; jt < 4; jt++) {
        #pragma unroll
        for (int cc = 0; cc < 2; cc++) {
            float v = h_d[jt * 4 + cc] + h_d[jt * 4 + 2 + cc];
            v += __shfl_xor_sync(FULL, v, 4);
            v += __shfl_xor_sync(FULL, v, 8);
            v += __shfl_xor_sync(FULL, v, 16);
            if (lane < 4)
                sfw[8 * jt + 2 * lane + cc] = v;
        }
    }
    __syncwarp();
    return sfw[lane];
}

// ---------------- fused kernel: hop0 + hop1 + combine + loss, per warp/b ----------------
__global__ __launch_bounds__(256, 2) void fused_kernel(
        const float* __restrict__ whh0, const float* __restrict__ wih0,
        const float* __restrict__ whh1, const float* __restrict__ wih1,
        const float* __restrict__ user_table,
        const int* __restrict__ users,
        const int* __restrict__ items,
        const int* __restrict__ lp0,
        const int* __restrict__ lp1,
        const float* __restrict__ ent_table,
        const float* __restrict__ agg_w,
        const float* __restrict__ agg_b,
        const int* __restrict__ ratings,
        float* __restrict__ out, int B) {
    __shared__ uint4 Bs2_0[16 * 32];   // Whh0^T fragments (8KB)
    __shared__ uint4 BsU_0[16 * 32];   // Wih0_u^T         (8KB)
    __shared__ uint4 Bs2_1[16 * 32];   // Whh1^T           (8KB)
    __shared__ uint4 BsU_1[16 * 32];   // Wih1_u^T         (8KB)
    __shared__ float aggT[32 * 32];    // combine weights  (4KB)
    __shared__ float aggb_sm[32];
    __shared__ float sf0[8][32];       // per-warp f0 staging
    __shared__ float sf1[8][32];       // per-warp f1 staging
    __shared__ float lred[8];
    __shared__ int   lastblk;

    int tid = threadIdx.x;
    // ---- fill fragment tables (once per CTA) ----
    for (int i = tid; i < 16 * 32; i += 256) {
        int nt = i >> 5;
        int ln = i & 31;
        int t = ln & 3, gq = ln >> 2;
        int g = 8 * nt + gq;
        const float* wg0 = whh0 + g * 32;
        Bs2_0[i] = make_uint4(bfpack(wg0[2 * t],      wg0[2 * t + 1]),
                              bfpack(wg0[2 * t + 8],  wg0[2 * t + 9]),
                              bfpack(wg0[2 * t + 16], wg0[2 * t + 17]),
                              bfpack(wg0[2 * t + 24], wg0[2 * t + 25]));
        const float* ug0 = wih0 + g * 64;
        BsU_0[i] = make_uint4(bfpack(ug0[2 * t],      ug0[2 * t + 1]),
                              bfpack(ug0[2 * t + 8],  ug0[2 * t + 9]),
                              bfpack(ug0[2 * t + 16], ug0[2 * t + 17]),
                              bfpack(ug0[2 * t + 24], ug0[2 * t + 25]));
        const float* wg1 = whh1 + g * 32;
        Bs2_1[i] = make_uint4(bfpack(wg1[2 * t],      wg1[2 * t + 1]),
                              bfpack(wg1[2 * t + 8],  wg1[2 * t + 9]),
                              bfpack(wg1[2 * t + 16], wg1[2 * t + 17]),
                              bfpack(wg1[2 * t + 24], wg1[2 * t + 25]));
        const float* ug1 = wih1 + g * 64;
        BsU_1[i] = make_uint4(bfpack(ug1[2 * t],      ug1[2 * t + 1]),
                              bfpack(ug1[2 * t + 8],  ug1[2 * t + 9]),
                              bfpack(ug1[2 * t + 16], ug1[2 * t + 17]),
                              bfpack(ug1[2 * t + 24], ug1[2 * t + 25]));
    }
    for (int i = tid; i < 32 * 32; i += 256) {
        int k = i >> 5, j = i & 31;
        aggT[i] = agg_w[j * 32 + k];
    }
    if (tid < 32) aggb_sm[tid] = agg_b[tid];
    __syncthreads();

    int wid = tid >> 5, lane = tid & 31;
    int r0 = lane >> 2, t = lane & 3;
    int p = lane & 15;

    int gw = blockIdx.x * 8 + wid;
    int TW = NBLK * 8;
    float loss_acc = 0.f;

    // ---- prologue: prefetch first iteration's indices ----
    int item = 0, user = 0;
    u32 ip0 = 0, ip1 = 0;
    if (gw < B) {
        item = __ldg(&items[gw]);
        user = __ldg(&users[gw]);
        const int* a0 = lp0 + (size_t)item * (P * 3) + p * 3;
        #pragma unroll
        for (int j = 0; j < 3; j++) ip0 |= ((u32)__ldg(&a0[j])) << (5 * j);
        const int* a1 = lp1 + (size_t)item * (P * 5) + p * 5;
        #pragma unroll
        for (int j = 0; j < 5; j++) ip1 |= ((u32)__ldg(&a1[j])) << (5 * j);
    }

    for (int b = gw; b < B; b += TW) {
        // ---- kick off next iteration's dependent index loads early ----
        int bn = b + TW;
        int item_n = 0, user_n = 0;
        u32 ip0_n = 0, ip1_n = 0;
        if (bn < B) {
            item_n = __ldg(&items[bn]);
            user_n = __ldg(&users[bn]);
            const int* a0 = lp0 + (size_t)item_n * (P * 3) + p * 3;
            #pragma unroll
            for (int j = 0; j < 3; j++) ip0_n |= ((u32)__ldg(&a0[j])) << (5 * j);
            const int* a1 = lp1 + (size_t)item_n * (P * 5) + p * 5;
            #pragma unroll
            for (int j = 0; j < 5; j++) ip1_n |= ((u32)__ldg(&a1[j])) << (5 * j);
        }

        u32 idxA0 = __shfl_sync(FULL, ip0, r0);
        u32 idxB0 = __shfl_sync(FULL, ip0, r0 + 8);
        u32 idxA1 = __shfl_sync(FULL, ip1, r0);
        u32 idxB1 = __shfl_sync(FULL, ip1, r0 + 8);

        // u fragments (shared by both hops): all 16 rows share u
        const float* uptr = user_table + (size_t)user * 32;
        float2 uv0 = *(const float2*)(uptr + 2 * t);
        float2 uv1 = *(const float2*)(uptr + 2 * t + 8);
        float2 uv2 = *(const float2*)(uptr + 2 * t + 16);
        float2 uv3 = *(const float2*)(uptr + 2 * t + 24);
        u32 au0 = bfpack(uv0.x, uv0.y), au1 = bfpack(uv1.x, uv1.y);
        u32 au2 = bfpack(uv2.x, uv2.y), au3 = bfpack(uv3.x, uv3.y);

        // ---- hop 0 LSTM (2 steps) ----
        float h_d[16];
        lstm16<2>(Bs2_0, BsU_0, g_Etab0, g_RT0,
                  au0, au1, au2, au3, idxA0, idxB0, t, lane, h_d);
        float f0 = reduce_stage(h_d, sf0[wid], lane);

        // ---- hop 1 LSTM (3 steps) ----
        lstm16<3>(Bs2_1, BsU_1, g_Etab1, g_RT1,
                  au0, au1, au2, au3, idxA1, idxB1, t, lane, h_d);
        float f1 = reduce_stage(h_d, sf1[wid], lane);

        // ---- combine: emb1 = (ent[item]+f0)@agg^T+b; emb2 = (emb1+f1)@agg^T+b ----
        float v = ent_table[(size_t)item * 32 + lane] + f0;
        float acc = aggb_sm[lane];
        #pragma unroll
        for (int k = 0; k < 32; k++)
            acc += __shfl_sync(FULL, v, k) * aggT[k * 32 + lane];

        v = acc + f1;
        acc = aggb_sm[lane];
        #pragma unroll
        for (int k = 0; k < 32; k++)
            acc += __shfl_sync(FULL, v, k) * aggT[k * 32 + lane];

        // score = dot(u, emb2)
        float prod = user_table[(size_t)user * 32 + lane] * acc;
        #pragma unroll
        for (int o = 16; o; o >>= 1) prod += __shfl_xor_sync(FULL, prod, o);

        if (lane == 0) {
            float s = prod;
            out[1 + b]     = 1.0f / (1.0f + __expf(-s));
            out[1 + B + b] = (float)item;
            float r    = (float)__ldg(&ratings[b]);
            float ls_p = fminf(s, 0.0f)  - log1pf(__expf(-fabsf(s)));
            float ls_n = fminf(-s, 0.0f) - log1pf(__expf(-fabsf(s)));
            loss_acc += -(r * ls_p + (1.0f - r) * ls_n);
        }

        item = item_n; user = user_n; ip0 = ip0_n; ip1 = ip1_n;
    }

    // ---- block loss partial + last-block final reduction ----
    if (lane == 0) lred[wid] = loss_acc;
    __syncthreads();
    if (tid == 0) {
        float s = 0.f;
        #pragma unroll
        for (int w = 0; w < 8; w++) s += lred[w];
        g_lossblk[blockIdx.x] = s;
        __threadfence();
        int n = atomicAdd(&g_donecnt, 1);
        lastblk = (n == NBLK - 1) ? 1 : 0;
    }
    __syncthreads();
    if (lastblk) {
        float s = 0.f;
        for (int i = tid; i < NBLK; i += 256) s += g_lossblk[i];
        lred[wid] = 0.f;   // reuse as scratch; reduce within block
        __syncthreads();
        #pragma unroll
        for (int o = 16; o; o >>= 1) s += __shfl_xor_sync(FULL, s, o);
        if (lane == 0) lred[wid] = s;
        __syncthreads();
        if (tid == 0) {
            float tot = 0.f;
            #pragma unroll
            for (int w = 0; w < 8; w++) tot += lred[w];
            out[0] = tot / (float)B;
        }
    }
}

// ---------------- launch ----------------
extern "C" void kernel_launch(void* const* d_in, const int* in_sizes, int n_in,
                              void* d_out, int out_size) {
    const float* user_table = (const float*)d_in[0];
    const float* ent_table  = (const float*)d_in[1];
    const float* rel_table  = (const float*)d_in[2];
    const float* w_ih0      = (const float*)d_in[3];
    const float* w_hh0      = (const float*)d_in[4];
    const float* b_ih0      = (const float*)d_in[5];
    const float* b_hh0      = (const float*)d_in[6];
    const float* w_ih1      = (const float*)d_in[7];
    const float* w_hh1      = (const float*)d_in[8];
    const float* b_ih1      = (const float*)d_in[9];
    const float* b_hh1      = (const float*)d_in[10];
    const float* agg_w      = (const float*)d_in[11];
    const float* agg_b      = (const float*)d_in[12];
    const int*   users      = (const int*)d_in[13];
    const int*   items      = (const int*)d_in[14];
    const int*   ratings    = (const int*)d_in[15];
    const int*   lp0        = (const int*)d_in[16];
    const int*   lp1        = (const int*)d_in[17];
    float*       out        = (float*)d_out;

    int B = in_sizes[13];

    precompute_tables_kernel<<<4, 1024>>>(rel_table, ent_table, w_ih0, w_ih1,
                                          b_ih0, b_hh0, b_ih1, b_hh1);
    precompute_rt_kernel<<<dim3(128, 2), 256>>>();
    fused_kernel<<<NBLK, 256>>>(w_hh0, w_ih0, w_hh1, w_ih1, user_table,
                                users, items, lp0, lp1, ent_table,
                                agg_w, agg_b, ratings, out, B);
}

// round 16
// speedup vs baseline: 1.6134x; 1.6134x over previous
#include <cuda_runtime.h>
#include <math.h>
#include <stdint.h>

#define FULL 0xffffffffu
typedef unsigned long long u64;
typedef unsigned int u32;

static constexpr int P    = 16;
static constexpr int NBLK = 296;

// ---------------- scratch (__device__ globals; no allocations) ----------------
__device__ float4 g_Rtab0[32 * 32];     // rel @ W_ih[:, :32]^T           (no bias)
__device__ float4 g_Etab0[32 * 32];     // bias + ent @ W_ih[:, 32:]^T    (bias folded)
__device__ float4 g_Rtab1[32 * 32];
__device__ float4 g_Etab1[32 * 32];
__device__ float4 g_RT0[1024 * 32];     // RT[ti*32+ri] = Rtab[ri] + Etab'[ti]
__device__ float4 g_RT1[1024 * 32];
__device__ float  g_lossblk[NBLK];

// ---------------- math helpers ----------------
__device__ __forceinline__ float tanha(float x) {
    float y; asm("tanh.approx.f32 %0,%1;" : "=f"(y) : "f"(x)); return y;
}
__device__ __forceinline__ float sigf(float x) {
    return fmaf(tanha(0.5f * x), 0.5f, 0.5f);
}
// pack {lo, hi} into bf16x2 (PTX: first source -> high half)
__device__ __forceinline__ u32 bfpack(float lo, float hi) {
    u32 d; asm("cvt.rn.bf16x2.f32 %0,%1,%2;" : "=r"(d) : "f"(hi), "f"(lo)); return d;
}
// D(16x8 f32) += A(16x16 bf16,row) @ B(16x8 bf16,col)
__device__ __forceinline__ void mma_bf16(float& d0, float& d1, float& d2, float& d3,
                                         u32 a0, u32 a1, u32 a2, u32 a3,
                                         u32 b0, u32 b1) {
    asm("mma.sync.aligned.m16n8k16.row.col.f32.bf16.bf16.f32 "
        "{%0,%1,%2,%3},{%4,%5,%6,%7},{%8,%9},{%0,%1,%2,%3};"
        : "+f"(d0), "+f"(d1), "+f"(d2), "+f"(d3)
        : "r"(a0), "r"(a1), "r"(a2), "r"(a3), "r"(b0), "r"(b1));
}

// ---------------- precompute E/R contribution tables ----------------
// FIXED: stage w in smem (coalesced global loads, pad-65 conflict-free reads).
// Previous version pushed ~524K uncoalesced L1 wavefronts through 4 SMs (68us).
__global__ __launch_bounds__(1024) void precompute_tables_kernel(
        const float* __restrict__ rel_table,
        const float* __restrict__ ent_table,
        const float* __restrict__ wih0,
        const float* __restrict__ wih1,
        const float* __restrict__ bih0,
        const float* __restrict__ bhh0,
        const float* __restrict__ bih1,
        const float* __restrict__ bhh1) {
    __shared__ float wsm[128 * 65];   // 33.3KB, padded stride 65
    int tid   = threadIdx.x;          // 1024
    int which = blockIdx.x;           // 0:Rtab0 1:Etab0 2:Rtab1 3:Etab1
    const float* w = (which < 2) ? wih0 : wih1;

    // coalesced load of w[128][64]
    for (int i = tid; i < 128 * 64; i += 1024)
        wsm[(i >> 6) * 65 + (i & 63)] = w[i];
    __syncthreads();

    int r    = tid >> 5;
    int lane = tid & 31;
    const float* src = (which & 1) ? ent_table : rel_table;
    int colofs       = (which & 1) ? 32 : 0;

    float4 acc = make_float4(0.f, 0.f, 0.f, 0.f);
    if (which & 1) {  // Etab: fold bias in
        const float* bi = (which < 2) ? bih0 : bih1;
        const float* bh = (which < 2) ? bhh0 : bhh1;
        acc.x = bi[lane]      + bh[lane];
        acc.y = bi[32 + lane] + bh[32 + lane];
        acc.z = bi[64 + lane] + bh[64 + lane];
        acc.w = bi[96 + lane] + bh[96 + lane];
    }
    #pragma unroll
    for (int k = 0; k < 32; k++) {
        float x = src[r * 32 + k];   // warp-broadcast load
        acc.x += x * wsm[(0 * 32 + lane) * 65 + colofs + k];
        acc.y += x * wsm[(1 * 32 + lane) * 65 + colofs + k];
        acc.z += x * wsm[(2 * 32 + lane) * 65 + colofs + k];
        acc.w += x * wsm[(3 * 32 + lane) * 65 + colofs + k];
    }
    float4* dst = (which == 0) ? g_Rtab0 : (which == 1) ? g_Etab0
                : (which == 2) ? g_Rtab1 : g_Etab1;
    dst[tid] = acc;
}

// ---------------- precompute fused RT tables: RT[ti*32+ri] = Rtab[ri] + Etab'[ti] ----------------
__global__ void precompute_rt_kernel() {
    int hop = blockIdx.y;
    int i = blockIdx.x * 256 + threadIdx.x;   // [0, 32768)
    int comb = i >> 5, j = i & 31;
    int ti = comb >> 5, r = comb & 31;
    const float4* Rt = hop ? g_Rtab1 : g_Rtab0;
    const float4* Et = hop ? g_Etab1 : g_Etab0;
    float4 a = Rt[r * 32 + j], b = Et[ti * 32 + j];
    (hop ? g_RT1 : g_RT0)[comb * 32 + j] =
        make_float4(a.x + b.x, a.y + b.y, a.z + b.z, a.w + b.w);
}

// ---------------- 16-path LSTM body (bf16 MMA, f32 tables) ----------------
// h_d out in D-fragment layout: flat = jt*4 + (pathB?2:0) + cc
template <int NSTEP>
__device__ __forceinline__ void lstm16(
        const uint4* __restrict__ Bs2, const uint4* __restrict__ BsU,
        const float4* __restrict__ Etab4, const float4* __restrict__ RTtab,
        u32 au0, u32 au1, u32 au2, u32 au3,
        u32 idxA, u32 idxB, int t, int lane, float h_d[16]) {
    float c_st[16];
    // ---- step 0: D init = Etab'[seed] (bias folded), U-term via broadcast MMA ----
    {
        const float4* EA = Etab4 + (idxA & 31) * 32;
        const float4* EB = Etab4 + (idxB & 31) * 32;
        #pragma unroll
        for (int jt = 0; jt < 4; jt++) {
            float G[4][4];
            #pragma unroll
            for (int cc = 0; cc < 2; cc++) {
                int j = 8 * jt + 2 * t + cc;
                float4 ea = EA[j];
                G[0][cc] = ea.x; G[1][cc] = ea.y; G[2][cc] = ea.z; G[3][cc] = ea.w;
                float4 eb = EB[j];
                G[0][2 + cc] = eb.x; G[1][2 + cc] = eb.y;
                G[2][2 + cc] = eb.z; G[3][2 + cc] = eb.w;
            }
            #pragma unroll
            for (int gt = 0; gt < 4; gt++) {
                int nt = jt + 4 * gt;
                uint4 bu = BsU[nt * 32 + lane];
                mma_bf16(G[gt][0], G[gt][1], G[gt][2], G[gt][3],
                         au0, au0, au1, au1, bu.x, bu.y);
                mma_bf16(G[gt][0], G[gt][1], G[gt][2], G[gt][3],
                         au2, au2, au3, au3, bu.z, bu.w);
            }
            #pragma unroll
            for (int dq = 0; dq < 4; dq++) {
                int ci = jt * 4 + dq;
                float c = sigf(G[0][dq]) * tanha(G[2][dq]);   // c_prev = 0
                c_st[ci] = c;
                h_d[ci] = sigf(G[3][dq]) * tanha(c);
            }
        }
    }
    // ---- recurrent steps ----
    #pragma unroll
    for (int s = 1; s < NSTEP; s++) {
        u32 ah[8];   // D-frag == A-frag for bf16 k16: same-lane packs only
        #pragma unroll
        for (int q = 0; q < 8; q++)
            ah[q] = bfpack(h_d[q * 2], h_d[q * 2 + 1]);

        u32 cA = (idxA >> (5 * (2 * s - 1))) & 1023;   // combined ti*32+ri
        u32 cB = (idxB >> (5 * (2 * s - 1))) & 1023;
        const float4* RTA = RTtab + cA * 32;
        const float4* RTB = RTtab + cB * 32;

        #pragma unroll
        for (int jt = 0; jt < 4; jt++) {
            float G[4][4];
            #pragma unroll
            for (int cc = 0; cc < 2; cc++) {
                int j = 8 * jt + 2 * t + cc;
                float4 ra = RTA[j];
                G[0][cc] = ra.x; G[1][cc] = ra.y; G[2][cc] = ra.z; G[3][cc] = ra.w;
                float4 rb = RTB[j];
                G[0][2 + cc] = rb.x; G[1][2 + cc] = rb.y;
                G[2][2 + cc] = rb.z; G[3][2 + cc] = rb.w;
            }
            #pragma unroll
            for (int gt = 0; gt < 4; gt++) {
                int nt = jt + 4 * gt;
                uint4 bb = Bs2[nt * 32 + lane];
                mma_bf16(G[gt][0], G[gt][1], G[gt][2], G[gt][3],
                         ah[0], ah[1], ah[2], ah[3], bb.x, bb.y);
                mma_bf16(G[gt][0], G[gt][1], G[gt][2], G[gt][3],
                         ah[4], ah[5], ah[6], ah[7], bb.z, bb.w);
            }
            #pragma unroll
            for (int dq = 0; dq < 4; dq++) {
                int ci = jt * 4 + dq;
                float c = sigf(G[1][dq]) * c_st[ci] + sigf(G[0][dq]) * tanha(G[2][dq]);
                c_st[ci] = c;
                h_d[ci] = sigf(G[3][dq]) * tanha(c);
            }
        }
    }
}

// reduce 16 paths -> per-b sum, stage to lane=j layout via smem, return f[lane]
__device__ __forceinline__ float reduce_stage(float h_d[16], float* sfw, int lane) {
    #pragma unroll
    for (int jt = 0; jt < 4; jt++) {
        #pragma unroll
        for (int cc = 0; cc < 2; cc++) {
            float v = h_d[jt * 4 + cc] + h_d[jt * 4 + 2 + cc];
            v += __shfl_xor_sync(FULL, v, 4);
            v += __shfl_xor_sync(FULL, v, 8);
            v += __shfl_xor_sync(FULL, v, 16);
            if (lane < 4)
                sfw[8 * jt + 2 * lane + cc] = v;
        }
    }
    __syncwarp();
    return sfw[lane];
}

// ---------------- fused kernel: hop0 LSTM + hop1 LSTM + combine, per warp/b ----------------
__global__ __launch_bounds__(256, 2) void fused_kernel(
        const float* __restrict__ whh0, const float* __restrict__ wih0,
        const float* __restrict__ whh1, const float* __restrict__ wih1,
        const float* __restrict__ user_table,
        const int* __restrict__ users,
        const int* __restrict__ items,
        const int* __restrict__ lp0,
        const int* __restrict__ lp1,
        const float* __restrict__ ent_table,
        const float* __restrict__ agg_w,
        const float* __restrict__ agg_b,
        const int* __restrict__ ratings,
        float* __restrict__ out, int B) {
    __shared__ uint4 Bs2_0[16 * 32];   // Whh0^T fragments (8KB)
    __shared__ uint4 BsU_0[16 * 32];   // Wih0_u^T         (8KB)
    __shared__ uint4 Bs2_1[16 * 32];   // Whh1^T           (8KB)
    __shared__ uint4 BsU_1[16 * 32];   // Wih1_u^T         (8KB)
    __shared__ float aggT[32 * 32];    // combine weights  (4KB)
    __shared__ float aggb_sm[32];
    __shared__ float sf0[8][32];       // per-warp f0 staging
    __shared__ float sf1[8][32];       // per-warp f1 staging
    __shared__ float lred[8];

    int tid = threadIdx.x;
    // ---- fill fragment tables (once per CTA) ----
    for (int i = tid; i < 16 * 32; i += 256) {
        int nt = i >> 5;
        int ln = i & 31;
        int t = ln & 3, gq = ln >> 2;
        int g = 8 * nt + gq;
        const float* wg0 = whh0 + g * 32;
        Bs2_0[i] = make_uint4(bfpack(wg0[2 * t],      wg0[2 * t + 1]),
                              bfpack(wg0[2 * t + 8],  wg0[2 * t + 9]),
                              bfpack(wg0[2 * t + 16], wg0[2 * t + 17]),
                              bfpack(wg0[2 * t + 24], wg0[2 * t + 25]));
        const float* ug0 = wih0 + g * 64;
        BsU_0[i] = make_uint4(bfpack(ug0[2 * t],      ug0[2 * t + 1]),
                              bfpack(ug0[2 * t + 8],  ug0[2 * t + 9]),
                              bfpack(ug0[2 * t + 16], ug0[2 * t + 17]),
                              bfpack(ug0[2 * t + 24], ug0[2 * t + 25]));
        const float* wg1 = whh1 + g * 32;
        Bs2_1[i] = make_uint4(bfpack(wg1[2 * t],      wg1[2 * t + 1]),
                              bfpack(wg1[2 * t + 8],  wg1[2 * t + 9]),
                              bfpack(wg1[2 * t + 16], wg1[2 * t + 17]),
                              bfpack(wg1[2 * t + 24], wg1[2 * t + 25]));
        const float* ug1 = wih1 + g * 64;
        BsU_1[i] = make_uint4(bfpack(ug1[2 * t],      ug1[2 * t + 1]),
                              bfpack(ug1[2 * t + 8],  ug1[2 * t + 9]),
                              bfpack(ug1[2 * t + 16], ug1[2 * t + 17]),
                              bfpack(ug1[2 * t + 24], ug1[2 * t + 25]));
    }
    for (int i = tid; i < 32 * 32; i += 256) {
        int k = i >> 5, j = i & 31;
        aggT[i] = agg_w[j * 32 + k];
    }
    if (tid < 32) aggb_sm[tid] = agg_b[tid];
    __syncthreads();

    int wid = tid >> 5, lane = tid & 31;
    int r0 = lane >> 2, t = lane & 3;

    int gw = blockIdx.x * 8 + wid;
    int TW = NBLK * 8;
    float loss_acc = 0.f;

    for (int b = gw; b < B; b += TW) {
        int item = __ldg(&items[b]);
        int user = __ldg(&users[b]);

        // pack 5-bit indices: lanes 0..15 own path lane
        int p = lane & 15;
        const int* lpb0 = lp0 + (size_t)item * (P * 3) + p * 3;
        u32 ip0 = 0;
        #pragma unroll
        for (int j = 0; j < 3; j++)
            ip0 |= ((u32)__ldg(&lpb0[j])) << (5 * j);
        const int* lpb1 = lp1 + (size_t)item * (P * 5) + p * 5;
        u32 ip1 = 0;
        #pragma unroll
        for (int j = 0; j < 5; j++)
            ip1 |= ((u32)__ldg(&lpb1[j])) << (5 * j);
        u32 idxA0 = __shfl_sync(FULL, ip0, r0);
        u32 idxB0 = __shfl_sync(FULL, ip0, r0 + 8);
        u32 idxA1 = __shfl_sync(FULL, ip1, r0);
        u32 idxB1 = __shfl_sync(FULL, ip1, r0 + 8);

        // u fragments (shared by both hops): all 16 rows share u
        const float* uptr = user_table + (size_t)user * 32;
        float2 uv0 = *(const float2*)(uptr + 2 * t);
        float2 uv1 = *(const float2*)(uptr + 2 * t + 8);
        float2 uv2 = *(const float2*)(uptr + 2 * t + 16);
        float2 uv3 = *(const float2*)(uptr + 2 * t + 24);
        u32 au0 = bfpack(uv0.x, uv0.y), au1 = bfpack(uv1.x, uv1.y);
        u32 au2 = bfpack(uv2.x, uv2.y), au3 = bfpack(uv3.x, uv3.y);

        // ---- hop 0 LSTM (2 steps) ----
        float h_d[16];
        lstm16<2>(Bs2_0, BsU_0, g_Etab0, g_RT0,
                  au0, au1, au2, au3, idxA0, idxB0, t, lane, h_d);
        float f0 = reduce_stage(h_d, sf0[wid], lane);

        // ---- hop 1 LSTM (3 steps) ----
        lstm16<3>(Bs2_1, BsU_1, g_Etab1, g_RT1,
                  au0, au1, au2, au3, idxA1, idxB1, t, lane, h_d);
        float f1 = reduce_stage(h_d, sf1[wid], lane);

        // ---- combine: emb1 = (ent[item]+f0)@agg^T+b; emb2 = (emb1+f1)@agg^T+b ----
        float v = ent_table[(size_t)item * 32 + lane] + f0;
        float acc = aggb_sm[lane];
        #pragma unroll
        for (int k = 0; k < 32; k++)
            acc += __shfl_sync(FULL, v, k) * aggT[k * 32 + lane];

        v = acc + f1;
        acc = aggb_sm[lane];
        #pragma unroll
        for (int k = 0; k < 32; k++)
            acc += __shfl_sync(FULL, v, k) * aggT[k * 32 + lane];

        // score = dot(u, emb2)
        float prod = user_table[(size_t)user * 32 + lane] * acc;
        #pragma unroll
        for (int o = 16; o; o >>= 1) prod += __shfl_xor_sync(FULL, prod, o);

        if (lane == 0) {
            float s = prod;
            out[1 + b]     = 1.0f / (1.0f + __expf(-s));
            out[1 + B + b] = (float)item;
            float r    = (float)__ldg(&ratings[b]);
            float ls_p = fminf(s, 0.0f)  - log1pf(__expf(-fabsf(s)));
            float ls_n = fminf(-s, 0.0f) - log1pf(__expf(-fabsf(s)));
            loss_acc += -(r * ls_p + (1.0f - r) * ls_n);
        }
    }

    if (lane == 0) lred[wid] = loss_acc;
    __syncthreads();
    if (tid == 0) {
        float s = 0.f;
        #pragma unroll
        for (int w = 0; w < 8; w++) s += lred[w];
        g_lossblk[blockIdx.x] = s;
    }
}

// ---------------- final loss reduction ----------------
__global__ void loss_kernel(float* __restrict__ out, int B, int nblk) {
    __shared__ float sm[512];
    int tid = threadIdx.x;
    float s = 0.f;
    for (int i = tid; i < nblk; i += 512) s += g_lossblk[i];
    sm[tid] = s;
    __syncthreads();
    for (int o = 256; o; o >>= 1) {
        if (tid < o) sm[tid] += sm[tid + o];
        __syncthreads();
    }
    if (tid == 0) out[0] = sm[0] / (float)B;
}

// ---------------- launch ----------------
extern "C" void kernel_launch(void* const* d_in, const int* in_sizes, int n_in,
                              void* d_out, int out_size) {
    const float* user_table = (const float*)d_in[0];
    const float* ent_table  = (const float*)d_in[1];
    const float* rel_table  = (const float*)d_in[2];
    const float* w_ih0      = (const float*)d_in[3];
    const float* w_hh0      = (const float*)d_in[4];
    const float* b_ih0      = (const float*)d_in[5];
    const float* b_hh0      = (const float*)d_in[6];
    const float* w_ih1      = (const float*)d_in[7];
    const float* w_hh1      = (const float*)d_in[8];
    const float* b_ih1      = (const float*)d_in[9];
    const float* b_hh1      = (const float*)d_in[10];
    const float* agg_w      = (const float*)d_in[11];
    const float* agg_b      = (const float*)d_in[12];
    const int*   users      = (const int*)d_in[13];
    const int*   items      = (const int*)d_in[14];
    const int*   ratings    = (const int*)d_in[15];
    const int*   lp0        = (const int*)d_in[16];
    const int*   lp1        = (const int*)d_in[17];
    float*       out        = (float*)d_out;

    int B = in_sizes[13];

    precompute_tables_kernel<<<4, 1024>>>(rel_table, ent_table, w_ih0, w_ih1,
                                          b_ih0, b_hh0, b_ih1, b_hh1);
    precompute_rt_kernel<<<dim3(128, 2), 256>>>();
    fused_kernel<<<NBLK, 256>>>(w_hh0, w_ih0, w_hh1, w_ih1, user_table,
                                users, items, lp0, lp1, ent_table,
                                agg_w, agg_b, ratings, out, B);
    loss_kernel<<<1, 512>>>(out, B, NBLK);
}

// round 17
// speedup vs baseline: 1.6199x; 1.0041x over previous
#include <cuda_runtime.h>
#include <math.h>
#include <stdint.h>

#define FULL 0xffffffffu
typedef unsigned long long u64;
typedef unsigned int u32;

static constexpr int P    = 16;
static constexpr int NBLK = 296;

// ---------------- scratch (__device__ globals; no allocations) ----------------
__device__ float4 g_Rtab0[32 * 32];     // rel @ W_ih[:, :32]^T           (no bias)
__device__ float4 g_Etab0[32 * 32];     // bias + ent @ W_ih[:, 32:]^T    (bias folded)
__device__ float4 g_Rtab1[32 * 32];
__device__ float4 g_Etab1[32 * 32];
__device__ float4 g_RT0[1024 * 32];     // RT[ti*32+ri] = Rtab[ri] + Etab'[ti]
__device__ float4 g_RT1[1024 * 32];
__device__ float  g_lossblk[NBLK];
__device__ int    g_donecnt;

// ---------------- math helpers ----------------
__device__ __forceinline__ float tanha(float x) {
    float y; asm("tanh.approx.f32 %0,%1;" : "=f"(y) : "f"(x)); return y;
}
__device__ __forceinline__ float sigf(float x) {
    return fmaf(tanha(0.5f * x), 0.5f, 0.5f);
}
// pack {lo, hi} into bf16x2 (PTX: first source -> high half)
__device__ __forceinline__ u32 bfpack(float lo, float hi) {
    u32 d; asm("cvt.rn.bf16x2.f32 %0,%1,%2;" : "=r"(d) : "f"(hi), "f"(lo)); return d;
}
// D(16x8 f32) += A(16x16 bf16,row) @ B(16x8 bf16,col)
__device__ __forceinline__ void mma_bf16(float& d0, float& d1, float& d2, float& d3,
                                         u32 a0, u32 a1, u32 a2, u32 a3,
                                         u32 b0, u32 b1) {
    asm("mma.sync.aligned.m16n8k16.row.col.f32.bf16.bf16.f32 "
        "{%0,%1,%2,%3},{%4,%5,%6,%7},{%8,%9},{%0,%1,%2,%3};"
        : "+f"(d0), "+f"(d1), "+f"(d2), "+f"(d3)
        : "r"(a0), "r"(a1), "r"(a2), "r"(a3), "r"(b0), "r"(b1));
}

// ---------------- precompute E/R contribution tables ----------------
// smem-staged w (coalesced global loads, pad-65 conflict-free reads).
__global__ __launch_bounds__(1024) void precompute_tables_kernel(
        const float* __restrict__ rel_table,
        const float* __restrict__ ent_table,
        const float* __restrict__ wih0,
        const float* __restrict__ wih1,
        const float* __restrict__ bih0,
        const float* __restrict__ bhh0,
        const float* __restrict__ bih1,
        const float* __restrict__ bhh1) {
    __shared__ float wsm[128 * 65];   // 33.3KB, padded stride 65
    int tid   = threadIdx.x;          // 1024
    int which = blockIdx.x;           // 0:Rtab0 1:Etab0 2:Rtab1 3:Etab1
    const float* w = (which < 2) ? wih0 : wih1;

    // coalesced load of w[128][64]
    for (int i = tid; i < 128 * 64; i += 1024)
        wsm[(i >> 6) * 65 + (i & 63)] = w[i];
    __syncthreads();

    int r    = tid >> 5;
    int lane = tid & 31;
    const float* src = (which & 1) ? ent_table : rel_table;
    int colofs       = (which & 1) ? 32 : 0;

    float4 acc = make_float4(0.f, 0.f, 0.f, 0.f);
    if (which & 1) {  // Etab: fold bias in
        const float* bi = (which < 2) ? bih0 : bih1;
        const float* bh = (which < 2) ? bhh0 : bhh1;
        acc.x = bi[lane]      + bh[lane];
        acc.y = bi[32 + lane] + bh[32 + lane];
        acc.z = bi[64 + lane] + bh[64 + lane];
        acc.w = bi[96 + lane] + bh[96 + lane];
    }
    #pragma unroll
    for (int k = 0; k < 32; k++) {
        float x = src[r * 32 + k];   // warp-broadcast load
        acc.x += x * wsm[(0 * 32 + lane) * 65 + colofs + k];
        acc.y += x * wsm[(1 * 32 + lane) * 65 + colofs + k];
        acc.z += x * wsm[(2 * 32 + lane) * 65 + colofs + k];
        acc.w += x * wsm[(3 * 32 + lane) * 65 + colofs + k];
    }
    float4* dst = (which == 0) ? g_Rtab0 : (which == 1) ? g_Etab0
                : (which == 2) ? g_Rtab1 : g_Etab1;
    dst[tid] = acc;
}

// ---------------- precompute fused RT tables: RT[ti*32+ri] = Rtab[ri] + Etab'[ti] ----------------
__global__ void precompute_rt_kernel() {
    if (blockIdx.x == 0 && blockIdx.y == 0 && threadIdx.x == 0)
        g_donecnt = 0;   // deterministic reset for fused kernel's last-block gate
    int hop = blockIdx.y;
    int i = blockIdx.x * 256 + threadIdx.x;   // [0, 32768)
    int comb = i >> 5, j = i & 31;
    int ti = comb >> 5, r = comb & 31;
    const float4* Rt = hop ? g_Rtab1 : g_Rtab0;
    const float4* Et = hop ? g_Etab1 : g_Etab0;
    float4 a = Rt[r * 32 + j], b = Et[ti * 32 + j];
    (hop ? g_RT1 : g_RT0)[comb * 32 + j] =
        make_float4(a.x + b.x, a.y + b.y, a.z + b.z, a.w + b.w);
}

// ---------------- 16-path LSTM body (bf16 MMA, f32 tables) ----------------
// h_d out in D-fragment layout: flat = jt*4 + (pathB?2:0) + cc
template <int NSTEP>
__device__ __forceinline__ void lstm16(
        const uint4* __restrict__ Bs2, const uint4* __restrict__ BsU,
        const float4* __restrict__ Etab4, const float4* __restrict__ RTtab,
        u32 au0, u32 au1, u32 au2, u32 au3,
        u32 idxA, u32 idxB, int t, int lane, float h_d[16]) {
    float c_st[16];
    // ---- step 0: D init = Etab'[seed] (bias folded), U-term via broadcast MMA ----
    {
        const float4* EA = Etab4 + (idxA & 31) * 32;
        const float4* EB = Etab4 + (idxB & 31) * 32;
        #pragma unroll
        for (int jt = 0; jt < 4; jt++) {
            float G[4][4];
            #pragma unroll
            for (int cc = 0; cc < 2; cc++) {
                int j = 8 * jt + 2 * t + cc;
                float4 ea = EA[j];
                G[0][cc] = ea.x; G[1][cc] = ea.y; G[2][cc] = ea.z; G[3][cc] = ea.w;
                float4 eb = EB[j];
                G[0][2 + cc] = eb.x; G[1][2 + cc] = eb.y;
                G[2][2 + cc] = eb.z; G[3][2 + cc] = eb.w;
            }
            #pragma unroll
            for (int gt = 0; gt < 4; gt++) {
                int nt = jt + 4 * gt;
                uint4 bu = BsU[nt * 32 + lane];
                mma_bf16(G[gt][0], G[gt][1], G[gt][2], G[gt][3],
                         au0, au0, au1, au1, bu.x, bu.y);
                mma_bf16(G[gt][0], G[gt][1], G[gt][2], G[gt][3],
                         au2, au2, au3, au3, bu.z, bu.w);
            }
            #pragma unroll
            for (int dq = 0; dq < 4; dq++) {
                int ci = jt * 4 + dq;
                float c = sigf(G[0][dq]) * tanha(G[2][dq]);   // c_prev = 0
                c_st[ci] = c;
                h_d[ci] = sigf(G[3][dq]) * tanha(c);
            }
        }
    }
    // ---- recurrent steps ----
    #pragma unroll
    for (int s = 1; s < NSTEP; s++) {
        u32 ah[8];   // D-frag == A-frag for bf16 k16: same-lane packs only
        #pragma unroll
        for (int q = 0; q < 8; q++)
            ah[q] = bfpack(h_d[q * 2], h_d[q * 2 + 1]);

        u32 cA = (idxA >> (5 * (2 * s - 1))) & 1023;   // combined ti*32+ri
        u32 cB = (idxB >> (5 * (2 * s - 1))) & 1023;
        const float4* RTA = RTtab + cA * 32;
        const float4* RTB = RTtab + cB * 32;

        #pragma unroll
        for (int jt = 0; jt < 4; jt++) {
            float G[4][4];
            #pragma unroll
            for (int cc = 0; cc < 2; cc++) {
                int j = 8 * jt + 2 * t + cc;
                float4 ra = RTA[j];
                G[0][cc] = ra.x; G[1][cc] = ra.y; G[2][cc] = ra.z; G[3][cc] = ra.w;
                float4 rb = RTB[j];
                G[0][2 + cc] = rb.x; G[1][2 + cc] = rb.y;
                G[2][2 + cc] = rb.z; G[3][2 + cc] = rb.w;
            }
            #pragma unroll
            for (int gt = 0; gt < 4; gt++) {
                int nt = jt + 4 * gt;
                uint4 bb = Bs2[nt * 32 + lane];
                mma_bf16(G[gt][0], G[gt][1], G[gt][2], G[gt][3],
                         ah[0], ah[1], ah[2], ah[3], bb.x, bb.y);
                mma_bf16(G[gt][0], G[gt][1], G[gt][2], G[gt][3],
                         ah[4], ah[5], ah[6], ah[7], bb.z, bb.w);
            }
            #pragma unroll
            for (int dq = 0; dq < 4; dq++) {
                int ci = jt * 4 + dq;
                float c = sigf(G[1][dq]) * c_st[ci] + sigf(G[0][dq]) * tanha(G[2][dq]);
                c_st[ci] = c;
                h_d[ci] = sigf(G[3][dq]) * tanha(c);
            }
        }
    }
}

// reduce 16 paths -> per-b sum, stage to lane=j layout via smem, return f[lane]
__device__ __forceinline__ float reduce_stage(float h_d[16], float* sfw, int lane) {
    #pragma unroll
    for (int jt = 0; jt < 4; jt++) {
        #pragma unroll
        for (int cc = 0; cc < 2; cc++) {
            float v = h_d[jt * 4 + cc] + h_d[jt * 4 + 2 + cc];
            v += __shfl_xor_sync(FULL, v, 4);
            v += __shfl_xor_sync(FULL, v, 8);
            v += __shfl_xor_sync(FULL, v, 16);
            if (lane < 4)
                sfw[8 * jt + 2 * lane + cc] = v;
        }
    }
    __syncwarp();
    return sfw[lane];
}

// ---------------- fused kernel: hop0 + hop1 + combine + final loss, per warp/b ----------------
__global__ __launch_bounds__(256, 2) void fused_kernel(
        const float* __restrict__ whh0, const float* __restrict__ wih0,
        const float* __restrict__ whh1, const float* __restrict__ wih1,
        const float* __restrict__ user_table,
        const int* __restrict__ users,
        const int* __restrict__ items,
        const int* __restrict__ lp0,
        const int* __restrict__ lp1,
        const float* __restrict__ ent_table,
        const float* __restrict__ agg_w,
        const float* __restrict__ agg_b,
        const int* __restrict__ ratings,
        float* __restrict__ out, int B) {
    __shared__ uint4 Bs2_0[16 * 32];   // Whh0^T fragments (8KB)
    __shared__ uint4 BsU_0[16 * 32];   // Wih0_u^T         (8KB)
    __shared__ uint4 Bs2_1[16 * 32];   // Whh1^T           (8KB)
    __shared__ uint4 BsU_1[16 * 32];   // Wih1_u^T         (8KB)
    __shared__ float aggT[32 * 32];    // combine weights  (4KB)
    __shared__ float aggb_sm[32];
    __shared__ float sf0[8][32];       // per-warp f0 staging
    __shared__ float sf1[8][32];       // per-warp f1 staging
    __shared__ float lred[8];
    __shared__ int   lastblk;

    int tid = threadIdx.x;
    // ---- fill fragment tables (once per CTA) ----
    for (int i = tid; i < 16 * 32; i += 256) {
        int nt = i >> 5;
        int ln = i & 31;
        int t = ln & 3, gq = ln >> 2;
        int g = 8 * nt + gq;
        const float* wg0 = whh0 + g * 32;
        Bs2_0[i] = make_uint4(bfpack(wg0[2 * t],      wg0[2 * t + 1]),
                              bfpack(wg0[2 * t + 8],  wg0[2 * t + 9]),
                              bfpack(wg0[2 * t + 16], wg0[2 * t + 17]),
                              bfpack(wg0[2 * t + 24], wg0[2 * t + 25]));
        const float* ug0 = wih0 + g * 64;
        BsU_0[i] = make_uint4(bfpack(ug0[2 * t],      ug0[2 * t + 1]),
                              bfpack(ug0[2 * t + 8],  ug0[2 * t + 9]),
                              bfpack(ug0[2 * t + 16], ug0[2 * t + 17]),
                              bfpack(ug0[2 * t + 24], ug0[2 * t + 25]));
        const float* wg1 = whh1 + g * 32;
        Bs2_1[i] = make_uint4(bfpack(wg1[2 * t],      wg1[2 * t + 1]),
                              bfpack(wg1[2 * t + 8],  wg1[2 * t + 9]),
                              bfpack(wg1[2 * t + 16], wg1[2 * t + 17]),
                              bfpack(wg1[2 * t + 24], wg1[2 * t + 25]));
        const float* ug1 = wih1 + g * 64;
        BsU_1[i] = make_uint4(bfpack(ug1[2 * t],      ug1[2 * t + 1]),
                              bfpack(ug1[2 * t + 8],  ug1[2 * t + 9]),
                              bfpack(ug1[2 * t + 16], ug1[2 * t + 17]),
                              bfpack(ug1[2 * t + 24], ug1[2 * t + 25]));
    }
    for (int i = tid; i < 32 * 32; i += 256) {
        int k = i >> 5, j = i & 31;
        aggT[i] = agg_w[j * 32 + k];
    }
    if (tid < 32) aggb_sm[tid] = agg_b[tid];
    __syncthreads();

    int wid = tid >> 5, lane = tid & 31;
    int r0 = lane >> 2, t = lane & 3;

    int gw = blockIdx.x * 8 + wid;
    int TW = NBLK * 8;
    float loss_acc = 0.f;

    for (int b = gw; b < B; b += TW) {
        int item = __ldg(&items[b]);
        int user = __ldg(&users[b]);

        // pack 5-bit indices: lanes 0..15 own path lane
        int p = lane & 15;
        const int* lpb0 = lp0 + (size_t)item * (P * 3) + p * 3;
        u32 ip0 = 0;
        #pragma unroll
        for (int j = 0; j < 3; j++)
            ip0 |= ((u32)__ldg(&lpb0[j])) << (5 * j);
        const int* lpb1 = lp1 + (size_t)item * (P * 5) + p * 5;
        u32 ip1 = 0;
        #pragma unroll
        for (int j = 0; j < 5; j++)
            ip1 |= ((u32)__ldg(&lpb1[j])) << (5 * j);
        u32 idxA0 = __shfl_sync(FULL, ip0, r0);
        u32 idxB0 = __shfl_sync(FULL, ip0, r0 + 8);
        u32 idxA1 = __shfl_sync(FULL, ip1, r0);
        u32 idxB1 = __shfl_sync(FULL, ip1, r0 + 8);

        // u fragments (shared by both hops): all 16 rows share u
        const float* uptr = user_table + (size_t)user * 32;
        float2 uv0 = *(const float2*)(uptr + 2 * t);
        float2 uv1 = *(const float2*)(uptr + 2 * t + 8);
        float2 uv2 = *(const float2*)(uptr + 2 * t + 16);
        float2 uv3 = *(const float2*)(uptr + 2 * t + 24);
        u32 au0 = bfpack(uv0.x, uv0.y), au1 = bfpack(uv1.x, uv1.y);
        u32 au2 = bfpack(uv2.x, uv2.y), au3 = bfpack(uv3.x, uv3.y);

        // ---- hop 0 LSTM (2 steps) ----
        float h_d[16];
        lstm16<2>(Bs2_0, BsU_0, g_Etab0, g_RT0,
                  au0, au1, au2, au3, idxA0, idxB0, t, lane, h_d);
        float f0 = reduce_stage(h_d, sf0[wid], lane);

        // ---- hop 1 LSTM (3 steps) ----
        lstm16<3>(Bs2_1, BsU_1, g_Etab1, g_RT1,
                  au0, au1, au2, au3, idxA1, idxB1, t, lane, h_d);
        float f1 = reduce_stage(h_d, sf1[wid], lane);

        // ---- combine: emb1 = (ent[item]+f0)@agg^T+b; emb2 = (emb1+f1)@agg^T+b ----
        float v = ent_table[(size_t)item * 32 + lane] + f0;
        float acc = aggb_sm[lane];
        #pragma unroll
        for (int k = 0; k < 32; k++)
            acc += __shfl_sync(FULL, v, k) * aggT[k * 32 + lane];

        v = acc + f1;
        acc = aggb_sm[lane];
        #pragma unroll
        for (int k = 0; k < 32; k++)
            acc += __shfl_sync(FULL, v, k) * aggT[k * 32 + lane];

        // score = dot(u, emb2)
        float prod = user_table[(size_t)user * 32 + lane] * acc;
        #pragma unroll
        for (int o = 16; o; o >>= 1) prod += __shfl_xor_sync(FULL, prod, o);

        if (lane == 0) {
            float s = prod;
            out[1 + b]     = 1.0f / (1.0f + __expf(-s));
            out[1 + B + b] = (float)item;
            float r    = (float)__ldg(&ratings[b]);
            float ls_p = fminf(s, 0.0f)  - log1pf(__expf(-fabsf(s)));
            float ls_n = fminf(-s, 0.0f) - log1pf(__expf(-fabsf(s)));
            loss_acc += -(r * ls_p + (1.0f - r) * ls_n);
        }
    }

    // ---- block loss partial + last-block final reduction (no extra launch) ----
    if (lane == 0) lred[wid] = loss_acc;
    __syncthreads();
    if (tid == 0) {
        float s = 0.f;
        #pragma unroll
        for (int w = 0; w < 8; w++) s += lred[w];
        g_lossblk[blockIdx.x] = s;
        __threadfence();
        int n = atomicAdd(&g_donecnt, 1);
        lastblk = (n == NBLK - 1) ? 1 : 0;
    }
    __syncthreads();
    if (lastblk) {
        float s = 0.f;
        for (int i = tid; i < NBLK; i += 256) s += g_lossblk[i];
        #pragma unroll
        for (int o = 16; o; o >>= 1) s += __shfl_xor_sync(FULL, s, o);
        if (lane == 0) lred[wid] = s;
        __syncthreads();
        if (tid == 0) {
            float tot = 0.f;
            #pragma unroll
            for (int w = 0; w < 8; w++) tot += lred[w];
            out[0] = tot / (float)B;
        }
    }
}

// ---------------- launch ----------------
extern "C" void kernel_launch(void* const* d_in, const int* in_sizes, int n_in,
                              void* d_out, int out_size) {
    const float* user_table = (const float*)d_in[0];
    const float* ent_table  = (const float*)d_in[1];
    const float* rel_table  = (const float*)d_in[2];
    const float* w_ih0      = (const float*)d_in[3];
    const float* w_hh0      = (const float*)d_in[4];
    const float* b_ih0      = (const float*)d_in[5];
    const float* b_hh0      = (const float*)d_in[6];
    const float* w_ih1      = (const float*)d_in[7];
    const float* w_hh1      = (const float*)d_in[8];
    const float* b_ih1      = (const float*)d_in[9];
    const float* b_hh1      = (const float*)d_in[10];
    const float* agg_w      = (const float*)d_in[11];
    const float* agg_b      = (const float*)d_in[12];
    const int*   users      = (const int*)d_in[13];
    const int*   items      = (const int*)d_in[14];
    const int*   ratings    = (const int*)d_in[15];
    const int*   lp0        = (const int*)d_in[16];
    const int*   lp1        = (const int*)d_in[17];
    float*       out        = (float*)d_out;

    int B = in_sizes[13];

    precompute_tables_kernel<<<4, 1024>>>(rel_table, ent_table, w_ih0, w_ih1,
                                          b_ih0, b_hh0, b_ih1, b_hh1);
    precompute_rt_kernel<<<dim3(128, 2), 256>>>();
    fused_kernel<<<NBLK, 256>>>(w_hh0, w_ih0, w_hh1, w_ih1, user_table,
                                users, items, lp0, lp1, ent_table,
                                agg_w, agg_b, ratings, out, B);
}